// round 6
// baseline (speedup 1.0000x reference)
#include <cuda_runtime.h>
#include <cstdint>

#define BN_EPS 1e-5f
#define NUM_GRAPHS 256

#define PSA 132                       // A pair-slab stride (pairs); 132%16=4 -> 2-phase LDS.64
#define SLAB 132                      // B pair-slab stride (pairs)
#define BT_FLOATS (16 * 4 * SLAB * 2) // 16896 floats per 128-col W4 tile
#define BT_BYTES  (BT_FLOATS * 4)     // 67584
#define W23P_FLOATS (8 * 4 * SLAB * 2) // 8448
#define W23P_BYTES (W23P_FLOATS * 4)

// ---------------- device-global scratch ----------------------------------------
__device__ float g_W1f[3 * 64];
__device__ float g_b1f[64];
__device__ float g_b23f[128];
__device__ __align__(16) float g_W23p[W23P_FLOATS];        // W23 pair-layout, tf32
__device__ __align__(16) float g_W4T[8 * BT_FLOATS];       // W4 per-tile pair-layout, tf32

// ---------------- PTX helpers ---------------------------------------------------
__device__ __forceinline__ uint32_t smem_u32(const void* p) {
    uint32_t a;
    asm("{ .reg .u64 t; cvta.to.shared.u64 t, %1; cvt.u32.u64 %0, t; }" : "=r"(a) : "l"(p));
    return a;
}
#define MBAR_INIT(addr, cnt) \
    asm volatile("mbarrier.init.shared.b64 [%0], %1;" :: "r"(addr), "r"(cnt) : "memory")
#define MBAR_EXPECT_TX(addr, bytes) \
    asm volatile("mbarrier.arrive.expect_tx.shared.b64 _, [%0], %1;" :: "r"(addr), "r"(bytes) : "memory")
#define MBAR_ARRIVE(addr) \
    asm volatile("mbarrier.arrive.release.cta.shared::cta.b64 _, [%0];" :: "r"(addr) : "memory")
#define MBAR_WAIT(addr, phase) do { \
    asm volatile("{\n\t.reg .pred P;\n\tWL_%=:\n\t" \
        "mbarrier.try_wait.parity.acquire.cta.shared::cta.b64 P, [%0], %1, 0x989680;\n\t" \
        "@P bra.uni WD_%=;\n\tbra.uni WL_%=;\n\tWD_%=:\n\t}" \
        :: "r"(addr), "r"(phase) : "memory"); \
} while (0)
#define FENCE_ASYNC_SHARED() asm volatile("fence.proxy.async.shared::cta;" ::: "memory")

__device__ __forceinline__ void bulk_g2s(uint32_t dst, const void* src, uint32_t bytes, uint32_t mbar) {
    asm volatile("cp.async.bulk.shared::cta.global.mbarrier::complete_tx::bytes [%0], [%1], %2, [%3];"
                 :: "r"(dst), "l"(src), "r"(bytes), "r"(mbar) : "memory");
}

__device__ __forceinline__ uint32_t f2tf32(float x) {
    uint32_t u;
    asm("cvt.rna.tf32.f32 %0, %1;" : "=r"(u) : "f"(x));
    return u;
}

__device__ __forceinline__ void mma_tf32(float* c, const uint32_t* a, uint32_t b0, uint32_t b1) {
    asm volatile("mma.sync.aligned.m16n8k8.row.col.f32.tf32.tf32.f32 "
                 "{%0,%1,%2,%3}, {%4,%5,%6,%7}, {%8,%9}, {%0,%1,%2,%3};"
                 : "+f"(c[0]), "+f"(c[1]), "+f"(c[2]), "+f"(c[3])
                 : "r"(a[0]), "r"(a[1]), "r"(a[2]), "r"(a[3]), "r"(b0), "r"(b1));
}

__device__ __forceinline__ unsigned encf(float f) {
    unsigned u = __float_as_uint(f);
    return (u & 0x80000000u) ? ~u : (u | 0x80000000u);
}

// ---------------- kernel 0: fold BN1; fuse W2@W3 (+BN3) -> pair layout ----------
__global__ void prep_kernel(const float* __restrict__ W1, const float* __restrict__ b1,
                            const float* __restrict__ g1, const float* __restrict__ be1,
                            const float* __restrict__ m1, const float* __restrict__ v1,
                            const float* __restrict__ W2, const float* __restrict__ b2,
                            const float* __restrict__ W3, const float* __restrict__ b3,
                            const float* __restrict__ g3, const float* __restrict__ be3,
                            const float* __restrict__ m3, const float* __restrict__ v3)
{
    __shared__ float W2s[64 * 64];
    int t = threadIdx.x;  // 128
    for (int i = t; i < 64 * 64; i += 128) W2s[i] = W2[i];

    if (t < 64) {
        float s = g1[t] * rsqrtf(v1[t] + BN_EPS);
        for (int i = 0; i < 3; i++) g_W1f[i * 64 + t] = W1[i * 64 + t] * s;
        g_b1f[t] = (b1[t] - m1[t]) * s + be1[t];
    }
    float w3c[64];
    #pragma unroll
    for (int k = 0; k < 64; k++) w3c[k] = W3[k * 128 + t];
    __syncthreads();

    float s3 = g3[t] * rsqrtf(v3[t] + BN_EPS);
    float accb = 0.f;
    #pragma unroll
    for (int k = 0; k < 64; k++) accb = fmaf(b2[k], w3c[k], accb);
    g_b23f[t] = (accb + b3[t] - m3[t]) * s3 + be3[t];

    for (int k = 0; k < 64; k++) {
        float acc = 0.f;
        #pragma unroll
        for (int kk = 0; kk < 64; kk++) acc = fmaf(W2s[k * 64 + kk], w3c[kk], acc);
        int k8 = k >> 3, kq = k & 3, h = (k & 7) >> 2;
        g_W23p[(((k8 * 4 + kq) * SLAB) + t) * 2 + h] = __uint_as_float(f2tf32(acc * s3));
    }
}

// ---------------- kernel 0b: W4 -> per-tile pair-layout tf32 images -------------
__global__ void w4t_kernel(const float* __restrict__ W4) {
    int id = blockIdx.x * 256 + threadIdx.x;   // 131072
    int nn = id & 1023, k = id >> 10;
    float v = W4[(size_t)k * 1024 + nn];
    int tile = nn >> 7, n = nn & 127;
    int k8 = k >> 3, kq = k & 3, h = (k & 7) >> 2;
    g_W4T[(size_t)tile * BT_FLOATS + (((k8 * 4 + kq) * SLAB) + n) * 2 + h] =
        __uint_as_float(f2tf32(v));
}

// ---------------- fused kernel --------------------------------------------------
// 256 threads (8 warps), 128 points/CTA.
// smem floats: As[0,16896) | B0[16896,33792) | B1[33792,50688)
//   xs[50688,51072) | w1s[51072,51264) | b1s[51264,51328) | b23s[51328,51456)
//   sb(int)[51456,51584) | mbars @51584 (5 x u64)
__global__ void __launch_bounds__(256, 1)
fused_kernel(const float* __restrict__ x, const int* __restrict__ batch,
             unsigned* __restrict__ out_enc, int n)
{
    extern __shared__ float sm[];
    float* As   = sm;
    float* B0   = sm + 16896;
    float* B1   = sm + 33792;
    float* xs   = sm + 50688;
    float* w1s  = sm + 51072;
    float* b1s  = sm + 51264;
    float* b23s = sm + 51328;
    int*   sb   = (int*)(sm + 51456);

    uint32_t smem_base = smem_u32(sm);
    uint32_t barFull0 = smem_base + 51584 * 4;
    uint32_t barFull1 = barFull0 + 8;
    uint32_t barFree0 = barFull0 + 16;
    uint32_t barFree1 = barFull0 + 24;
    uint32_t slowBar  = barFull0 + 32;
    uint32_t bAddr[2] = { smem_base + 16896 * 4, smem_base + 33792 * 4 };
    float* Bbuf[2] = { B0, B1 };

    int t    = threadIdx.x;
    int wid  = t >> 5;
    int lane = t & 31;
    int p0   = blockIdx.x * 128;
    int mhalf = wid >> 2;
    int nblk  = wid & 3;
    int r0 = lane >> 2, kq = lane & 3;

    if (t == 0) {
        MBAR_INIT(barFull0, 1); MBAR_INIT(barFull1, 1);
        MBAR_INIT(barFree0, 8); MBAR_INIT(barFree1, 8);
        MBAR_INIT(slowBar, 8);
    }
    __syncthreads();
    FENCE_ASYNC_SHARED();

    if (t == 0) {
        MBAR_EXPECT_TX(barFull0, BT_BYTES);
        bulk_g2s(bAddr[0], (const void*)g_W4T, BT_BYTES, barFull0);
        MBAR_EXPECT_TX(barFull1, W23P_BYTES);
        bulk_g2s(bAddr[1], (const void*)g_W23p, W23P_BYTES, barFull1);
    }

    // ---- small loads ----
    for (int i = t; i < 384; i += 256) {
        int p = i / 3, c = i - p * 3;
        xs[c * 128 + p] = (p0 + p < n) ? x[(size_t)(p0 + p) * 3 + c] : 0.f;
    }
    if (t < 192) w1s[t] = g_W1f[t];
    if (t < 64)  b1s[t] = g_b1f[t];
    if (t < 128) b23s[t] = g_b23f[t];
    if (t < 128) {
        int p = p0 + t;
        sb[t] = (p < n) ? batch[p] : -1;
    }
    __syncthreads();

    // preload x for this thread's 8 rows
    float xr[8][3];
    #pragma unroll
    for (int mbk = 0; mbk < 4; mbk++)
        #pragma unroll
        for (int j = 0; j < 2; j++) {
            int row = mhalf * 64 + mbk * 16 + r0 + 8 * j;
            xr[mbk * 2 + j][0] = xs[row];
            xr[mbk * 2 + j][1] = xs[128 + row];
            xr[mbk * 2 + j][2] = xs[256 + row];
        }

    // ---- phase A: h3 = relu(h1 @ W23 + b23); h1 built in regs; A-pair store ----
    MBAR_WAIT(barFull1, 0);   // W23p ready
    {
        float acc[4][4][4];
        #pragma unroll
        for (int i = 0; i < 4; i++)
            #pragma unroll
            for (int j = 0; j < 4; j++)
                #pragma unroll
                for (int r = 0; r < 4; r++) acc[i][j][r] = 0.f;

        const float2* Wp = (const float2*)B1;
        #pragma unroll 2
        for (int k8 = 0; k8 < 8; k8++) {
            int k1 = k8 * 8 + kq, k2 = k1 + 4;
            float wa0 = w1s[k1], wa1 = w1s[64 + k1], wa2 = w1s[128 + k1], ba = b1s[k1];
            float wb0 = w1s[k2], wb1 = w1s[64 + k2], wb2 = w1s[128 + k2], bb = b1s[k2];
            uint32_t a[4][4];
            #pragma unroll
            for (int mbk = 0; mbk < 4; mbk++) {
                #pragma unroll
                for (int j = 0; j < 2; j++) {
                    const float* xv = xr[mbk * 2 + j];
                    float va = fmaf(xv[0], wa0, fmaf(xv[1], wa1, fmaf(xv[2], wa2, ba)));
                    float vb = fmaf(xv[0], wb0, fmaf(xv[1], wb1, fmaf(xv[2], wb2, bb)));
                    a[mbk][j]     = f2tf32(fmaxf(va, 0.f));
                    a[mbk][j + 2] = f2tf32(fmaxf(vb, 0.f));
                }
            }
            #pragma unroll
            for (int nbk = 0; nbk < 4; nbk++) {
                float2 bv = Wp[(k8 * 4 + kq) * SLAB + nblk * 32 + nbk * 8 + r0];
                uint32_t b0 = __float_as_uint(bv.x), b1v = __float_as_uint(bv.y);
                #pragma unroll
                for (int mbk = 0; mbk < 4; mbk++)
                    mma_tf32(acc[mbk][nbk], a[mbk], b0, b1v);
            }
        }

        // epilogue: bias+relu+tf32, scatter into A pair layout
        int h = kq >> 1;
        int kqe = (kq & 1) * 2;
        #pragma unroll
        for (int mbk = 0; mbk < 4; mbk++) {
            int ra = mhalf * 64 + mbk * 16 + r0;
            #pragma unroll
            for (int nbk = 0; nbk < 4; nbk++) {
                int c0 = nblk * 32 + nbk * 8 + kq * 2;
                int s0 = ((nblk * 4 + nbk) * 4 + kqe) * PSA;
                int s1 = s0 + PSA;
                float v00 = __uint_as_float(f2tf32(fmaxf(acc[mbk][nbk][0] + b23s[c0], 0.f)));
                float v01 = __uint_as_float(f2tf32(fmaxf(acc[mbk][nbk][1] + b23s[c0 + 1], 0.f)));
                float v10 = __uint_as_float(f2tf32(fmaxf(acc[mbk][nbk][2] + b23s[c0], 0.f)));
                float v11 = __uint_as_float(f2tf32(fmaxf(acc[mbk][nbk][3] + b23s[c0 + 1], 0.f)));
                As[(s0 + ra) * 2 + h]       = v00;
                As[(s1 + ra) * 2 + h]       = v01;
                As[(s0 + ra + 8) * 2 + h]   = v10;
                As[(s1 + ra + 8) * 2 + h]   = v11;
            }
        }
    }
    __syncthreads();          // As visible to all; W23p reads done
    if (t == 0) {             // B1 <- tile 1
        FENCE_ASYNC_SHARED();
        MBAR_EXPECT_TX(barFull1, BT_BYTES);
        bulk_g2s(bAddr[1], (const void*)(g_W4T + BT_FLOATS), BT_BYTES, barFull1);
    }

    // ---- phase B: 8 N-tiles, de-lockstepped ----
    bool fast = (sb[0] >= 0) && (sb[0] == sb[127]);
    const float NEG_INF = __int_as_float(0xff800000);
    const float2* As2 = (const float2*)As;
    unsigned* outg = fast ? &out_enc[(size_t)sb[0] * 1024] : out_enc;
    int scount = 0;

    #pragma unroll 1
    for (int nt = 0; nt < 8; nt++) {
        int buf = nt & 1;
        uint32_t barFull = buf ? barFull1 : barFull0;
        uint32_t barFree = buf ? barFree1 : barFree0;
        MBAR_WAIT(barFull, ((nt >> 1) & 1) ^ buf);
        const float2* Bp = (const float2*)Bbuf[buf];

        float acc[4][4][4];
        #pragma unroll
        for (int i = 0; i < 4; i++)
            #pragma unroll
            for (int j = 0; j < 4; j++)
                #pragma unroll
                for (int r = 0; r < 4; r++) acc[i][j][r] = 0.f;

        #pragma unroll 4
        for (int k8 = 0; k8 < 16; k8++) {
            uint32_t a[4][4];
            #pragma unroll
            for (int mbk = 0; mbk < 4; mbk++) {
                int row = mhalf * 64 + mbk * 16 + r0;
                float2 va = As2[(k8 * 4 + kq) * PSA + row];
                float2 vb = As2[(k8 * 4 + kq) * PSA + row + 8];
                a[mbk][0] = __float_as_uint(va.x);
                a[mbk][1] = __float_as_uint(vb.x);
                a[mbk][2] = __float_as_uint(va.y);
                a[mbk][3] = __float_as_uint(vb.y);
            }
            #pragma unroll
            for (int nbk = 0; nbk < 4; nbk++) {
                float2 bv = Bp[(k8 * 4 + kq) * SLAB + nblk * 32 + nbk * 8 + r0];
                uint32_t b0 = __float_as_uint(bv.x), b1v = __float_as_uint(bv.y);
                #pragma unroll
                for (int mbk = 0; mbk < 4; mbk++)
                    mma_tf32(acc[mbk][nbk], a[mbk], b0, b1v);
            }
        }

        int n0 = nt * 128;
        if (fast) {
            // this warp is done reading B[buf]
            if (lane == 0) MBAR_ARRIVE(barFree);
            // warp 0: wait for all warps, then prefetch nt+2 into freed buffer
            if (wid == 0 && nt + 2 < 8) {
                MBAR_WAIT(barFree, (nt >> 1) & 1);
                if (lane == 0) {
                    FENCE_ASYNC_SHARED();
                    MBAR_EXPECT_TX(barFull, BT_BYTES);
                    bulk_g2s(bAddr[buf], (const void*)(g_W4T + (size_t)(nt + 2) * BT_FLOATS),
                             BT_BYTES, barFull);
                }
            }
            // warp-local column max + direct atomics (no cross-warp combine)
            #pragma unroll
            for (int nbk = 0; nbk < 4; nbk++) {
                float e = NEG_INF, o = NEG_INF;
                #pragma unroll
                for (int mbk = 0; mbk < 4; mbk++) {
                    e = fmaxf(e, fmaxf(acc[mbk][nbk][0], acc[mbk][nbk][2]));
                    o = fmaxf(o, fmaxf(acc[mbk][nbk][1], acc[mbk][nbk][3]));
                }
                #pragma unroll
                for (int d = 4; d <= 16; d <<= 1) {
                    e = fmaxf(e, __shfl_xor_sync(0xffffffffu, e, d));
                    o = fmaxf(o, __shfl_xor_sync(0xffffffffu, o, d));
                }
                if (r0 == 0) {
                    int c = n0 + nblk * 32 + nbk * 8 + kq * 2;
                    atomicMax(&outg[c], encf(e));
                    atomicMax(&outg[c + 1], encf(o));
                }
            }
        } else {
            // slow path (CTA-uniform): block sync via phase-counted mbarrier
            __syncwarp();
            if (lane == 0) MBAR_ARRIVE(slowBar);
            MBAR_WAIT(slowBar, scount & 1); scount++;   // all reads of B[buf] done
            float* Cs = Bbuf[buf];
            #pragma unroll
            for (int mbk = 0; mbk < 4; mbk++) {
                int ra = mhalf * 64 + mbk * 16 + r0;
                #pragma unroll
                for (int nbk = 0; nbk < 4; nbk++) {
                    int c0 = nblk * 32 + nbk * 8 + kq * 2;
                    *(float2*)&Cs[ra * PSA + c0]       = make_float2(acc[mbk][nbk][0], acc[mbk][nbk][1]);
                    *(float2*)&Cs[(ra + 8) * PSA + c0] = make_float2(acc[mbk][nbk][2], acc[mbk][nbk][3]);
                }
            }
            __syncwarp();
            if (lane == 0) MBAR_ARRIVE(slowBar);
            MBAR_WAIT(slowBar, scount & 1); scount++;   // staging visible
            {
                int col = t & 127, half = t >> 7;
                int cur = -2; float best = 0.f;
                unsigned* obase = &out_enc[n0 + col];
                for (int m = half * 64; m < half * 64 + 64; m++) {
                    int g = sb[m];
                    float v = Cs[m * PSA + col];
                    if (g != cur) {
                        if (cur >= 0) atomicMax(obase + (size_t)cur * 1024, encf(best));
                        cur = g; best = v;
                    } else best = fmaxf(best, v);
                }
                if (cur >= 0) atomicMax(obase + (size_t)cur * 1024, encf(best));
            }
            __syncwarp();
            if (lane == 0) MBAR_ARRIVE(barFree);        // scan done -> buffer free
            if (wid == 0 && nt + 2 < 8) {
                MBAR_WAIT(barFree, (nt >> 1) & 1);
                if (lane == 0) {
                    FENCE_ASYNC_SHARED();
                    MBAR_EXPECT_TX(barFull, BT_BYTES);
                    bulk_g2s(bAddr[buf], (const void*)(g_W4T + (size_t)(nt + 2) * BT_FLOATS),
                             BT_BYTES, barFull);
                }
            }
        }
    }
}

// ---------------- init / decode ------------------------------------------------
__global__ void init_out(unsigned* out_enc, int total) {
    int i = blockIdx.x * 256 + threadIdx.x;
    if (i < total) out_enc[i] = 0x007FFFFFu;   // encf(-inf)
}

__global__ void decode_out(float* out, const float* __restrict__ b4, int total) {
    int i = blockIdx.x * 256 + threadIdx.x;
    if (i < total) {
        unsigned u = ((unsigned*)out)[i];
        unsigned d = (u & 0x80000000u) ? (u ^ 0x80000000u) : ~u;
        out[i] = __uint_as_float(d) + b4[i & 1023];
    }
}

// ---------------- launch -------------------------------------------------------
extern "C" void kernel_launch(void* const* d_in, const int* in_sizes, int n_in,
                              void* d_out, int out_size)
{
    const float* x     = (const float*)d_in[0];
    const int*   batch = (const int*)  d_in[1];
    const float* W1  = (const float*)d_in[2];
    const float* b1  = (const float*)d_in[3];
    const float* g1  = (const float*)d_in[4];
    const float* be1 = (const float*)d_in[5];
    const float* m1  = (const float*)d_in[6];
    const float* v1  = (const float*)d_in[7];
    const float* W2  = (const float*)d_in[8];
    const float* b2  = (const float*)d_in[9];
    const float* W3  = (const float*)d_in[10];
    const float* b3  = (const float*)d_in[11];
    const float* g3  = (const float*)d_in[12];
    const float* be3 = (const float*)d_in[13];
    const float* m3  = (const float*)d_in[14];
    const float* v3  = (const float*)d_in[15];
    const float* W4  = (const float*)d_in[16];
    const float* b4  = (const float*)d_in[17];

    int n  = in_sizes[0] / 3;
    int NT = (n + 127) / 128;

    size_t smB = (51584 + 16) * 4;   // 206400 B
    cudaFuncSetAttribute(fused_kernel, cudaFuncAttributeMaxDynamicSharedMemorySize, (int)smB);

    prep_kernel<<<1, 128>>>(W1, b1, g1, be1, m1, v1, W2, b2, W3, b3, g3, be3, m3, v3);
    w4t_kernel<<<512, 256>>>(W4);

    int blocks_o = (out_size + 255) / 256;
    init_out<<<blocks_o, 256>>>((unsigned*)d_out, out_size);

    fused_kernel<<<NT, 256, smB>>>(x, batch, (unsigned*)d_out, n);

    decode_out<<<blocks_o, 256>>>((float*)d_out, b4, out_size);
}

// round 7
// speedup vs baseline: 1.2601x; 1.2601x over previous
#include <cuda_runtime.h>
#include <cstdint>

#define BN_EPS 1e-5f
#define NUM_GRAPHS 256

#define P_A 132                       // As row pitch (floats)
#define SLAB 132                      // B pair-layout slab stride (pairs)
#define BT_FLOATS (16 * 4 * SLAB * 2) // 16896 floats per 128-col W4 tile
#define BT_BYTES  (BT_FLOATS * 4)     // 67584
#define W23P_FLOATS (8 * 4 * SLAB * 2)
#define W23P_BYTES (W23P_FLOATS * 4)

// ---------------- device-global scratch ----------------------------------------
__device__ float g_W1f[3 * 64];
__device__ float g_b1f[64];
__device__ float g_b23f[128];
__device__ __align__(16) float g_W23p[W23P_FLOATS];
__device__ __align__(16) float g_W4T[8 * BT_FLOATS];

// ---------------- PTX helpers ---------------------------------------------------
__device__ __forceinline__ uint32_t smem_u32(const void* p) {
    uint32_t a;
    asm("{ .reg .u64 t; cvta.to.shared.u64 t, %1; cvt.u32.u64 %0, t; }" : "=r"(a) : "l"(p));
    return a;
}
#define MBAR_INIT(addr, cnt) \
    asm volatile("mbarrier.init.shared.b64 [%0], %1;" :: "r"(addr), "r"(cnt) : "memory")
#define MBAR_EXPECT_TX(addr, bytes) \
    asm volatile("mbarrier.arrive.expect_tx.shared.b64 _, [%0], %1;" :: "r"(addr), "r"(bytes) : "memory")
#define MBAR_ARRIVE(addr) \
    asm volatile("mbarrier.arrive.release.cta.shared::cta.b64 _, [%0];" :: "r"(addr) : "memory")
#define MBAR_WAIT(addr, phase) do { \
    asm volatile("{\n\t.reg .pred P;\n\tWL_%=:\n\t" \
        "mbarrier.try_wait.parity.acquire.cta.shared::cta.b64 P, [%0], %1, 0x989680;\n\t" \
        "@P bra.uni WD_%=;\n\tbra.uni WL_%=;\n\tWD_%=:\n\t}" \
        :: "r"(addr), "r"(phase) : "memory"); \
} while (0)
#define FENCE_ASYNC_SHARED() asm volatile("fence.proxy.async.shared::cta;" ::: "memory")

__device__ __forceinline__ void bulk_g2s(uint32_t dst, const void* src, uint32_t bytes, uint32_t mbar) {
    asm volatile("cp.async.bulk.shared::cta.global.mbarrier::complete_tx::bytes [%0], [%1], %2, [%3];"
                 :: "r"(dst), "l"(src), "r"(bytes), "r"(mbar) : "memory");
}

__device__ __forceinline__ uint32_t f2tf32(float x) {
    uint32_t u;
    asm("cvt.rna.tf32.f32 %0, %1;" : "=r"(u) : "f"(x));
    return u;
}

__device__ __forceinline__ void mma_tf32(float* c, const uint32_t* a, uint32_t b0, uint32_t b1) {
    asm volatile("mma.sync.aligned.m16n8k8.row.col.f32.tf32.tf32.f32 "
                 "{%0,%1,%2,%3}, {%4,%5,%6,%7}, {%8,%9}, {%0,%1,%2,%3};"
                 : "+f"(c[0]), "+f"(c[1]), "+f"(c[2]), "+f"(c[3])
                 : "r"(a[0]), "r"(a[1]), "r"(a[2]), "r"(a[3]), "r"(b0), "r"(b1));
}

__device__ __forceinline__ unsigned encf(float f) {
    unsigned u = __float_as_uint(f);
    return (u & 0x80000000u) ? ~u : (u | 0x80000000u);
}

// ---------------- kernel 0: fold BN1; fuse W2@W3 (+BN3) -> pair layout ----------
__global__ void prep_kernel(const float* __restrict__ W1, const float* __restrict__ b1,
                            const float* __restrict__ g1, const float* __restrict__ be1,
                            const float* __restrict__ m1, const float* __restrict__ v1,
                            const float* __restrict__ W2, const float* __restrict__ b2,
                            const float* __restrict__ W3, const float* __restrict__ b3,
                            const float* __restrict__ g3, const float* __restrict__ be3,
                            const float* __restrict__ m3, const float* __restrict__ v3)
{
    __shared__ float W2s[64 * 64];
    int t = threadIdx.x;  // 128
    for (int i = t; i < 64 * 64; i += 128) W2s[i] = W2[i];

    if (t < 64) {
        float s = g1[t] * rsqrtf(v1[t] + BN_EPS);
        for (int i = 0; i < 3; i++) g_W1f[i * 64 + t] = W1[i * 64 + t] * s;
        g_b1f[t] = (b1[t] - m1[t]) * s + be1[t];
    }
    float w3c[64];
    #pragma unroll
    for (int k = 0; k < 64; k++) w3c[k] = W3[k * 128 + t];
    __syncthreads();

    float s3 = g3[t] * rsqrtf(v3[t] + BN_EPS);
    float accb = 0.f;
    #pragma unroll
    for (int k = 0; k < 64; k++) accb = fmaf(b2[k], w3c[k], accb);
    g_b23f[t] = (accb + b3[t] - m3[t]) * s3 + be3[t];

    for (int k = 0; k < 64; k++) {
        float acc = 0.f;
        #pragma unroll
        for (int kk = 0; kk < 64; kk++) acc = fmaf(W2s[k * 64 + kk], w3c[kk], acc);
        int k8 = k >> 3, kq = k & 3, h = (k & 7) >> 2;
        g_W23p[(((k8 * 4 + kq) * SLAB) + t) * 2 + h] = __uint_as_float(f2tf32(acc * s3));
    }
}

// ---------------- kernel 0b: W4 -> per-tile pair-layout tf32 images -------------
__global__ void w4t_kernel(const float* __restrict__ W4) {
    int id = blockIdx.x * 256 + threadIdx.x;   // 131072
    int nn = id & 1023, k = id >> 10;
    float v = W4[(size_t)k * 1024 + nn];
    int tile = nn >> 7, n = nn & 127;
    int k8 = k >> 3, kq = k & 3, h = (k & 7) >> 2;
    g_W4T[(size_t)tile * BT_FLOATS + (((k8 * 4 + kq) * SLAB) + n) * 2 + h] =
        __uint_as_float(f2tf32(v));
}

// ---------------- fused kernel --------------------------------------------------
// 256 threads (8 warps), 128 points/CTA.
// smem floats: As[0,16896) | B0[16896,33792) | B1[33792,50688)
//   xs[50688,51072) | w1s[51072,51264) | b1s[51264,51328) | b23s[51328,51456)
//   sb(int)[51456,51584) | mbars @51584 (4 x u64)
__global__ void __launch_bounds__(256, 1)
fused_kernel(const float* __restrict__ x, const int* __restrict__ batch,
             unsigned* __restrict__ out_enc, int n)
{
    extern __shared__ float sm[];
    float* As   = sm;
    float* B0   = sm + 16896;
    float* B1   = sm + 33792;
    float* xs   = sm + 50688;
    float* w1s  = sm + 51072;
    float* b1s  = sm + 51264;
    float* b23s = sm + 51328;
    int*   sb   = (int*)(sm + 51456);

    uint32_t smem_base = smem_u32(sm);
    uint32_t barFull0 = smem_base + 51584 * 4;
    uint32_t barFull1 = barFull0 + 8;
    uint32_t barFree0 = barFull0 + 16;
    uint32_t barFree1 = barFull0 + 24;
    uint32_t bAddr[2] = { smem_base + 16896 * 4, smem_base + 33792 * 4 };
    float* Bbuf[2] = { B0, B1 };

    int t    = threadIdx.x;
    int wid  = t >> 5;
    int lane = t & 31;
    int p0   = blockIdx.x * 128;
    int r0 = lane >> 2, kq = lane & 3;

    if (t == 0) {
        MBAR_INIT(barFull0, 1); MBAR_INIT(barFull1, 1);
        MBAR_INIT(barFree0, 4); MBAR_INIT(barFree1, 4);
    }
    __syncthreads();
    FENCE_ASYNC_SHARED();

    if (t == 0) {
        MBAR_EXPECT_TX(barFull0, BT_BYTES);
        bulk_g2s(bAddr[0], (const void*)g_W4T, BT_BYTES, barFull0);
        MBAR_EXPECT_TX(barFull1, W23P_BYTES);
        bulk_g2s(bAddr[1], (const void*)g_W23p, W23P_BYTES, barFull1);
    }

    // ---- small loads ----
    for (int i = t; i < 384; i += 256) {
        int p = i / 3, c = i - p * 3;
        xs[c * 128 + p] = (p0 + p < n) ? x[(size_t)(p0 + p) * 3 + c] : 0.f;
    }
    if (t < 192) w1s[t] = g_W1f[t];
    if (t < 64)  b1s[t] = g_b1f[t];
    if (t < 128) b23s[t] = g_b23f[t];
    if (t < 128) {
        int p = p0 + t;
        sb[t] = (p < n) ? batch[p] : -1;
    }
    __syncthreads();

    // ---- phase A (round-5 proven): h3 = relu(h1 @ W23 + b23) -------------------
    {
        int mhalf = wid >> 2;
        int nblk  = wid & 3;
        float xr[8][3];
        #pragma unroll
        for (int mbk = 0; mbk < 4; mbk++)
            #pragma unroll
            for (int j = 0; j < 2; j++) {
                int row = mhalf * 64 + mbk * 16 + r0 + 8 * j;
                xr[mbk * 2 + j][0] = xs[row];
                xr[mbk * 2 + j][1] = xs[128 + row];
                xr[mbk * 2 + j][2] = xs[256 + row];
            }

        MBAR_WAIT(barFull1, 0);   // W23p ready
        float acc[4][4][4];
        #pragma unroll
        for (int i = 0; i < 4; i++)
            #pragma unroll
            for (int j = 0; j < 4; j++)
                #pragma unroll
                for (int r = 0; r < 4; r++) acc[i][j][r] = 0.f;

        const float2* Wp = (const float2*)B1;
        #pragma unroll 2
        for (int k8 = 0; k8 < 8; k8++) {
            int k1 = k8 * 8 + kq, k2 = k1 + 4;
            float wa0 = w1s[k1], wa1 = w1s[64 + k1], wa2 = w1s[128 + k1], ba = b1s[k1];
            float wb0 = w1s[k2], wb1 = w1s[64 + k2], wb2 = w1s[128 + k2], bb = b1s[k2];
            uint32_t a[4][4];
            #pragma unroll
            for (int mbk = 0; mbk < 4; mbk++) {
                #pragma unroll
                for (int j = 0; j < 2; j++) {
                    const float* xv = xr[mbk * 2 + j];
                    float va = fmaf(xv[0], wa0, fmaf(xv[1], wa1, fmaf(xv[2], wa2, ba)));
                    float vb = fmaf(xv[0], wb0, fmaf(xv[1], wb1, fmaf(xv[2], wb2, bb)));
                    a[mbk][j]     = f2tf32(fmaxf(va, 0.f));
                    a[mbk][j + 2] = f2tf32(fmaxf(vb, 0.f));
                }
            }
            #pragma unroll
            for (int nbk = 0; nbk < 4; nbk++) {
                float2 bv = Wp[(k8 * 4 + kq) * SLAB + nblk * 32 + nbk * 8 + r0];
                uint32_t b0 = __float_as_uint(bv.x), b1v = __float_as_uint(bv.y);
                #pragma unroll
                for (int mbk = 0; mbk < 4; mbk++)
                    mma_tf32(acc[mbk][nbk], a[mbk], b0, b1v);
            }
        }

        // epilogue: bias + relu + tf32, write As[m][k] pitch P_A
        #pragma unroll
        for (int mbk = 0; mbk < 4; mbk++) {
            int ra = mhalf * 64 + mbk * 16 + r0;
            #pragma unroll
            for (int nbk = 0; nbk < 4; nbk++) {
                int c0 = nblk * 32 + nbk * 8 + kq * 2;
                float bb0 = b23s[c0], bb1 = b23s[c0 + 1];
                uint2 v0, v1;
                v0.x = f2tf32(fmaxf(acc[mbk][nbk][0] + bb0, 0.f));
                v0.y = f2tf32(fmaxf(acc[mbk][nbk][1] + bb1, 0.f));
                v1.x = f2tf32(fmaxf(acc[mbk][nbk][2] + bb0, 0.f));
                v1.y = f2tf32(fmaxf(acc[mbk][nbk][3] + bb1, 0.f));
                *(uint2*)&As[ra * P_A + c0]       = v0;
                *(uint2*)&As[(ra + 8) * P_A + c0] = v1;
            }
        }
    }
    __syncthreads();          // As visible; W23p reads done
    if (t == 0) {             // B1 <- tile 1
        FENCE_ASYNC_SHARED();
        MBAR_EXPECT_TX(barFull1, BT_BYTES);
        bulk_g2s(bAddr[1], (const void*)(g_W4T + BT_FLOATS), BT_BYTES, barFull1);
    }

    bool fast = (sb[0] >= 0) && (sb[0] == sb[127]);
    const float NEG_INF = __int_as_float(0xff800000);
    const uint32_t* Asu = (const uint32_t*)As;

    if (fast) {
        // ======== fast path: 2 warp-groups on alternating tiles, no block sync ==
        int g   = wid >> 2;          // group 0/1
        int wig = wid & 3;           // warp in group
        int mh  = wig >> 1;          // M half (64 rows)
        int nh  = wig & 1;           // N half (64 cols)
        uint32_t barFull = g ? barFull1 : barFull0;
        uint32_t barFree = g ? barFree1 : barFree0;
        const float2* Bp = (const float2*)Bbuf[g];
        unsigned* outg = &out_enc[(size_t)sb[0] * 1024];
        int fullPar = g;             // B1's tile-1 load completes at parity 1
        int freePar = 0;

        #pragma unroll 1
        for (int j = 0; j < 4; j++) {
            int nt = g + 2 * j;
            MBAR_WAIT(barFull, fullPar); fullPar ^= 1;

            float acc[4][8][4];
            #pragma unroll
            for (int i = 0; i < 4; i++)
                #pragma unroll
                for (int q = 0; q < 8; q++)
                    #pragma unroll
                    for (int r = 0; r < 4; r++) acc[i][q][r] = 0.f;

            #pragma unroll 2
            for (int k8 = 0; k8 < 16; k8++) {
                int k0 = k8 * 8;
                uint32_t a[4][4];
                #pragma unroll
                for (int mbk = 0; mbk < 4; mbk++) {
                    const uint32_t* ap = &Asu[(mh * 64 + mbk * 16 + r0) * P_A + k0 + kq];
                    a[mbk][0] = ap[0];
                    a[mbk][1] = ap[8 * P_A];
                    a[mbk][2] = ap[4];
                    a[mbk][3] = ap[8 * P_A + 4];
                }
                #pragma unroll
                for (int nbk = 0; nbk < 8; nbk++) {
                    float2 bv = Bp[(k8 * 4 + kq) * SLAB + nh * 64 + nbk * 8 + r0];
                    uint32_t b0 = __float_as_uint(bv.x), b1v = __float_as_uint(bv.y);
                    #pragma unroll
                    for (int mbk = 0; mbk < 4; mbk++)
                        mma_tf32(acc[mbk][nbk], a[mbk], b0, b1v);
                }
            }
            __syncwarp();
            if (lane == 0) MBAR_ARRIVE(barFree);   // this warp's B reads done

            // group leader: wait all 4 warps, then prefetch tile nt+2
            if (wig == 0 && j + 1 < 4) {
                MBAR_WAIT(barFree, freePar);
                if (lane == 0) {
                    FENCE_ASYNC_SHARED();
                    MBAR_EXPECT_TX(barFull, BT_BYTES);
                    bulk_g2s(bAddr[g], (const void*)(g_W4T + (size_t)(nt + 2) * BT_FLOATS),
                             BT_BYTES, barFull);
                }
            }
            freePar ^= 1;

            // warp-local column max + direct atomics (overlaps other group's MMAs)
            int n0 = nt * 128;
            #pragma unroll
            for (int nbk = 0; nbk < 8; nbk++) {
                float e = NEG_INF, o = NEG_INF;
                #pragma unroll
                for (int mbk = 0; mbk < 4; mbk++) {
                    e = fmaxf(e, fmaxf(acc[mbk][nbk][0], acc[mbk][nbk][2]));
                    o = fmaxf(o, fmaxf(acc[mbk][nbk][1], acc[mbk][nbk][3]));
                }
                #pragma unroll
                for (int d = 4; d <= 16; d <<= 1) {
                    e = fmaxf(e, __shfl_xor_sync(0xffffffffu, e, d));
                    o = fmaxf(o, __shfl_xor_sync(0xffffffffu, o, d));
                }
                if (r0 == 0) {
                    int c = n0 + nh * 64 + nbk * 8 + kq * 2;
                    atomicMax(&outg[c], encf(e));
                    atomicMax(&outg[c + 1], encf(o));
                }
            }
        }
    } else {
        // ======== slow path: verbatim round-5 lock-step (boundary / pad CTAs) ===
        int mhalf = wid >> 2;
        int nblk  = wid & 3;
        #pragma unroll 1
        for (int nt = 0; nt < 8; nt++) {
            int buf = nt & 1;
            uint32_t barFull = buf ? barFull1 : barFull0;
            MBAR_WAIT(barFull, ((nt >> 1) & 1) ^ buf);
            const float2* Bp = (const float2*)Bbuf[buf];

            float acc[4][4][4];
            #pragma unroll
            for (int i = 0; i < 4; i++)
                #pragma unroll
                for (int q = 0; q < 4; q++)
                    #pragma unroll
                    for (int r = 0; r < 4; r++) acc[i][q][r] = 0.f;

            #pragma unroll 2
            for (int k8 = 0; k8 < 16; k8++) {
                int k0 = k8 * 8;
                uint32_t a[4][4];
                #pragma unroll
                for (int mbk = 0; mbk < 4; mbk++) {
                    const uint32_t* ap = &Asu[(mhalf * 64 + mbk * 16 + r0) * P_A + k0 + kq];
                    a[mbk][0] = ap[0];
                    a[mbk][1] = ap[8 * P_A];
                    a[mbk][2] = ap[4];
                    a[mbk][3] = ap[8 * P_A + 4];
                }
                #pragma unroll
                for (int nbk = 0; nbk < 4; nbk++) {
                    float2 bv = Bp[(k8 * 4 + kq) * SLAB + nblk * 32 + nbk * 8 + r0];
                    uint32_t b0 = __float_as_uint(bv.x), b1v = __float_as_uint(bv.y);
                    #pragma unroll
                    for (int mbk = 0; mbk < 4; mbk++)
                        mma_tf32(acc[mbk][nbk], a[mbk], b0, b1v);
                }
            }
            __syncthreads();   // all reads of B[buf] complete

            int n0 = nt * 128;
            float* Cs = Bbuf[buf];
            #pragma unroll
            for (int mbk = 0; mbk < 4; mbk++) {
                int ra = mhalf * 64 + mbk * 16 + r0;
                #pragma unroll
                for (int nbk = 0; nbk < 4; nbk++) {
                    int c0 = nblk * 32 + nbk * 8 + kq * 2;
                    *(float2*)&Cs[ra * P_A + c0]       = make_float2(acc[mbk][nbk][0], acc[mbk][nbk][1]);
                    *(float2*)&Cs[(ra + 8) * P_A + c0] = make_float2(acc[mbk][nbk][2], acc[mbk][nbk][3]);
                }
            }
            __syncthreads();
            {
                int col = t & 127, half = t >> 7;
                int cur = -2; float best = 0.f;
                unsigned* obase = &out_enc[n0 + col];
                for (int m = half * 64; m < half * 64 + 64; m++) {
                    int g2 = sb[m];
                    float v = Cs[m * P_A + col];
                    if (g2 != cur) {
                        if (cur >= 0) atomicMax(obase + (size_t)cur * 1024, encf(best));
                        cur = g2; best = v;
                    } else best = fmaxf(best, v);
                }
                if (cur >= 0) atomicMax(obase + (size_t)cur * 1024, encf(best));
            }
            __syncthreads();
            if (t == 0 && nt + 2 < 8) {
                FENCE_ASYNC_SHARED();
                MBAR_EXPECT_TX(barFull, BT_BYTES);
                bulk_g2s(bAddr[buf], (const void*)(g_W4T + (size_t)(nt + 2) * BT_FLOATS),
                         BT_BYTES, barFull);
            }
        }
    }
}

// ---------------- init / decode ------------------------------------------------
__global__ void init_out(unsigned* out_enc, int total) {
    int i = blockIdx.x * 256 + threadIdx.x;
    if (i < total) out_enc[i] = 0x007FFFFFu;   // encf(-inf)
}

__global__ void decode_out(float* out, const float* __restrict__ b4, int total) {
    int i = blockIdx.x * 256 + threadIdx.x;
    if (i < total) {
        unsigned u = ((unsigned*)out)[i];
        unsigned d = (u & 0x80000000u) ? (u ^ 0x80000000u) : ~u;
        out[i] = __uint_as_float(d) + b4[i & 1023];
    }
}

// ---------------- launch -------------------------------------------------------
extern "C" void kernel_launch(void* const* d_in, const int* in_sizes, int n_in,
                              void* d_out, int out_size)
{
    const float* x     = (const float*)d_in[0];
    const int*   batch = (const int*)  d_in[1];
    const float* W1  = (const float*)d_in[2];
    const float* b1  = (const float*)d_in[3];
    const float* g1  = (const float*)d_in[4];
    const float* be1 = (const float*)d_in[5];
    const float* m1  = (const float*)d_in[6];
    const float* v1  = (const float*)d_in[7];
    const float* W2  = (const float*)d_in[8];
    const float* b2  = (const float*)d_in[9];
    const float* W3  = (const float*)d_in[10];
    const float* b3  = (const float*)d_in[11];
    const float* g3  = (const float*)d_in[12];
    const float* be3 = (const float*)d_in[13];
    const float* m3  = (const float*)d_in[14];
    const float* v3  = (const float*)d_in[15];
    const float* W4  = (const float*)d_in[16];
    const float* b4  = (const float*)d_in[17];

    int n  = in_sizes[0] / 3;
    int NT = (n + 127) / 128;

    size_t smB = (51584 + 16) * 4;   // 206400 B
    cudaFuncSetAttribute(fused_kernel, cudaFuncAttributeMaxDynamicSharedMemorySize, (int)smB);

    prep_kernel<<<1, 128>>>(W1, b1, g1, be1, m1, v1, W2, b2, W3, b3, g3, be3, m3, v3);
    w4t_kernel<<<512, 256>>>(W4);

    int blocks_o = (out_size + 255) / 256;
    init_out<<<blocks_o, 256>>>((unsigned*)d_out, out_size);

    fused_kernel<<<NT, 256, smB>>>(x, batch, (unsigned*)d_out, n);

    decode_out<<<blocks_o, 256>>>((float*)d_out, b4, out_size);
}